// round 16
// baseline (speedup 1.0000x reference)
#include <cuda_runtime.h>
#include <cuda_fp16.h>
#include <mma.h>
#include <cstdint>

using namespace nvcuda;

// ---------------------------------------------------------------------------
// SGConv on GB300 — fp16 pull hops + lean wmma GEMM (global fp16 W + bias
// tile prebuilt once; zero per-block staging, zero block syncs in GEMM).
// N=100000, E=800000, D=128, 3 hops.
// ---------------------------------------------------------------------------

#define NN   100000
#define EE   800000
#define DIM  128
#define CAP  96          // in-edge slot capacity per node

#define GEMM_FULL_TILES 781              // 781*128 = 99968 nodes via wmma
#define TAIL_BASE (GEMM_FULL_TILES * 128)
#define TAIL_N    (NN - TAIL_BASE)       // 32 nodes via scalar kernel

__device__ int    g_cnt [NN];
__device__ int    g_col [NN * CAP];     // 38.4 MB
__device__ float  g_dinv[NN];
__device__ __align__(16) __half2 g_hh1[NN * 64];  // fp16 features A (25.6 MB)
__device__ __align__(16) __half2 g_hh2[NN * 64];  // fp16 features B (25.6 MB)
__device__ __align__(16) __half  g_Wh  [DIM * DIM];   // fp16 W (32 KB)
__device__ __align__(16) float   g_biasT[16 * DIM];   // bias broadcast tile

// ---------------------------------------------------------------------------
// Fused init: zero counts, convert x -> fp16, convert W -> fp16, build biasT.
// One grid over NN*32 float4-slots; low-index threads do the small jobs too.
__global__ void init_kernel(const float4* __restrict__ x,
                            const float*  __restrict__ W,
                            const float*  __restrict__ bias) {
    int i = blockIdx.x * blockDim.x + threadIdx.x;
    if (i < NN * 32) {
        float4 v = x[i];
        g_hh1[i * 2 + 0] = __floats2half2_rn(v.x, v.y);
        g_hh1[i * 2 + 1] = __floats2half2_rn(v.z, v.w);
    }
    if (i < NN) g_cnt[i] = 0;
    if (i < DIM * DIM / 4) {               // W convert, float4 granularity
        float4 w = *(const float4*)(W + i * 4);
        __half* dst = g_Wh + i * 4;
        dst[0] = __float2half(w.x);
        dst[1] = __float2half(w.y);
        dst[2] = __float2half(w.z);
        dst[3] = __float2half(w.w);
    }
    if (i < 16 * DIM) {                    // bias broadcast tile (16 rows)
        g_biasT[i] = bias[i & (DIM - 1)];
    }
}

__global__ void fill_kernel(const int* __restrict__ ei) {
    int e = blockIdx.x * blockDim.x + threadIdx.x;
    if (e < EE) {
        int src = ei[e];
        int dst = ei[EE + e];
        int pos = atomicAdd(&g_cnt[dst], 1);
        if (pos < CAP) g_col[dst * CAP + pos] = src;
    }
}

__global__ void dinv_kernel() {
    int i = blockIdx.x * blockDim.x + threadIdx.x;
    if (i < NN) g_dinv[i] = rsqrtf((float)(g_cnt[i] + 1));  // +1 self-loop
}

// One warp per node; lane l owns elements [4l..4l+3]. fp16 gathers, fp32 acc.
__global__ void pull_kernel(int hinSel, int outSel) {
    const __half2* __restrict__ hin = (hinSel == 0) ? g_hh1 : g_hh2;
    int t    = blockIdx.x * blockDim.x + threadIdx.x;
    int n    = t >> 5;
    int lane = t & 31;
    if (n >= NN) return;

    int   cnt = g_cnt[n];
    if (cnt > CAP) cnt = CAP;
    float dn  = g_dinv[n];

    const int myOff = n * 64 + lane * 2;
    float2 s0 = __half22float2(hin[myOff]);
    float2 s1 = __half22float2(hin[myOff + 1]);
    float  ss = dn * dn;
    float4 acc = make_float4(s0.x * ss, s0.y * ss, s1.x * ss, s1.y * ss);

    int base = n * CAP;
    for (int c0 = 0; c0 < cnt; c0 += 32) {
        int m = cnt - c0; if (m > 32) m = 32;
        int   myCol = 0;
        float myNrm = 0.0f;
        if (lane < m) {
            myCol = g_col[base + c0 + lane];
            myNrm = g_dinv[myCol];
        }
        #pragma unroll 4
        for (int i = 0; i < m; i++) {
            int   s  = __shfl_sync(0xffffffffu, myCol, i);
            float nr = __shfl_sync(0xffffffffu, myNrm, i) * dn;
            int off = s * 64 + lane * 2;
            float2 f0 = __half22float2(hin[off]);
            float2 f1 = __half22float2(hin[off + 1]);
            acc.x += f0.x * nr; acc.y += f0.y * nr;
            acc.z += f1.x * nr; acc.w += f1.y * nr;
        }
    }

    __half2* hout = (outSel == 0) ? g_hh1 : g_hh2;
    hout[myOff]     = __floats2half2_rn(acc.x, acc.y);
    hout[myOff + 1] = __floats2half2_rn(acc.z, acc.w);
}

// ---------------------------------------------------------------------------
// Lean wmma GEMM: out[128x128 tile] = H(fp16,global) * Wh^T(fp16,global) + b.
// 8 warps; warp w owns rows [w*16, w*16+16). No smem, no syncs.
// matrix_b col_major over row-major g_Wh[n][k] (ld=DIM) gives B(k,n)=W[n][k].
__global__ __launch_bounds__(256) void gemm_wmma_kernel(float* __restrict__ out) {
    int warp = threadIdx.x >> 5;
    int rowBase = blockIdx.x * 128 + warp * 16;

    wmma::fragment<wmma::accumulator, 16, 16, 16, float> c[8];
#pragma unroll
    for (int j = 0; j < 8; j++)
        wmma::load_matrix_sync(c[j], g_biasT + j * 16, DIM, wmma::mem_row_major);

    const __half* H = (const __half*)g_hh2;
#pragma unroll
    for (int kk = 0; kk < 8; kk++) {
        wmma::fragment<wmma::matrix_a, 16, 16, 16, __half, wmma::row_major> a;
        wmma::load_matrix_sync(a, H + (size_t)rowBase * DIM + kk * 16, DIM);
#pragma unroll
        for (int j = 0; j < 8; j++) {
            wmma::fragment<wmma::matrix_b, 16, 16, 16, __half, wmma::col_major> bfr;
            wmma::load_matrix_sync(bfr, g_Wh + j * 16 * DIM + kk * 16, DIM);
            wmma::mma_sync(c[j], a, bfr, c[j]);
        }
    }

#pragma unroll
    for (int j = 0; j < 8; j++)
        wmma::store_matrix_sync(out + (size_t)rowBase * DIM + j * 16, c[j],
                                DIM, wmma::mem_row_major);
}

// Scalar tail for the last TAIL_N nodes (block per node, 128 threads).
__global__ void tail_linear_kernel(const float* __restrict__ W,
                                   const float* __restrict__ bias,
                                   float* __restrict__ out) {
    __shared__ float sh[DIM];
    int node = TAIL_BASE + blockIdx.x;
    int j    = threadIdx.x;
    const __half* H = (const __half*)g_hh2;
    sh[j] = __half2float(H[(size_t)node * DIM + j]);
    __syncthreads();

    const float4* Wr = (const float4*)(W + j * DIM);
    float acc = bias[j];
#pragma unroll
    for (int k = 0; k < DIM / 4; k++) {
        float4 w = Wr[k];
        acc += w.x * sh[k * 4] + w.y * sh[k * 4 + 1]
             + w.z * sh[k * 4 + 2] + w.w * sh[k * 4 + 3];
    }
    out[(size_t)node * DIM + j] = acc;
}

// ---------------------------------------------------------------------------
extern "C" void kernel_launch(void* const* d_in, const int* in_sizes, int n_in,
                              void* d_out, int out_size) {
    const float* x   = (const float*)d_in[0];
    const int*   ei  = (const int*)d_in[1];
    const float* W   = (const float*)d_in[2];
    const float* b   = (const float*)d_in[3];
    float*       out = (float*)d_out;
    const float4* x4 = (const float4*)x;

    const int TB = 256;
    const int nodeBlocks = (NN + TB - 1) / TB;
    const int edgeBlocks = (EE + TB - 1) / TB;
    const int initBlocks = (NN * 32 + TB - 1) / TB;
    const int PB = 128;
    const int pullBlocks = (NN * 32 + PB - 1) / PB;   // warp per node

    init_kernel<<<initBlocks, TB>>>(x4, W, b);
    fill_kernel<<<edgeBlocks, TB>>>(ei);
    dinv_kernel<<<nodeBlocks, TB>>>();

    // hops: hh1 -> hh2 -> hh1 -> hh2 (all fp16)
    pull_kernel<<<pullBlocks, PB>>>(0, 1);
    pull_kernel<<<pullBlocks, PB>>>(1, 0);
    pull_kernel<<<pullBlocks, PB>>>(0, 1);

    gemm_wmma_kernel  <<<GEMM_FULL_TILES, 256>>>(out);
    tail_linear_kernel<<<TAIL_N, DIM>>>(W, b, out);
}